// round 9
// baseline (speedup 1.0000x reference)
#include <cuda_runtime.h>
#include <cstdint>

#define BATCH 16
#define NV    20000
#define FIN   64
#define COUT  64
#define KNB   16

#define NBM_STRIDE 68                         // pad: bank = 4g+t+4j, conflict-free
#define SMEM_W_BYTES   32768                  // 2*8*8*64 uint32
#define SMEM_NBM_BYTES (128 * NBM_STRIDE * 4) // 34816
#define SMEM_NID_OFF   (SMEM_W_BYTES + SMEM_NBM_BYTES)
#define SMEM_TOTAL     (SMEM_NID_OFF + 128 * KNB * 4)   // 75776

// Weights in mma-fragment order: [mat(2)][ks(8)][nt(8)][lane(32)][2] tf32 bits
__device__ uint32_t g_wfrag[2 * 8 * 8 * 32 * 2];

// ---------------------------------------------------------------------------
// Pre-kernel: swizzle Wx/Wn into m16n8k8 B-fragment order (tf32)
// ---------------------------------------------------------------------------
__global__ void wfrag_build_kernel(const float* __restrict__ Wx,
                                   const float* __restrict__ Wn)
{
    int i = blockIdx.x * 256 + threadIdx.x;        // 0..16383
    int j    =  i        & 1;
    int lane = (i >> 1)  & 31;
    int nt   = (i >> 6)  & 7;
    int ks   = (i >> 9)  & 7;
    int mat  =  i >> 12;
    int k = (lane & 3) + 4 * j + 8 * ks;
    int n = (lane >> 2) + 8 * nt;
    const float* W = mat ? Wn : Wx;
    float v = W[k * COUT + n];
    uint32_t tv;
    asm("cvt.rna.tf32.f32 %0, %1;" : "=r"(tv) : "f"(v));
    g_wfrag[i] = tv;
}

// ---------------------------------------------------------------------------
// Fused kernel: gather nb_mean(x) into smem, then dual tf32 tensor GEMM:
//   out = x@Wx + nb_mean@Wn + bias       (single pass, no scratch tensor)
// CTA = 128 verts x one batch, 8 warps. Warp = 16 verts x 64 cols, K=64.
// ---------------------------------------------------------------------------
__global__ __launch_bounds__(256, 2)
void convnet_fused_tc(const float* __restrict__ x,
                      const float* __restrict__ bias,
                      const int*   __restrict__ neighbor,
                      float*       __restrict__ out)
{
    extern __shared__ char smraw[];
    uint32_t* sW   = (uint32_t*)smraw;
    float*    sNbm = (float*)(smraw + SMEM_W_BYTES);
    int*      sNid = (int*)(smraw + SMEM_NID_OFF);

    const int tid  = threadIdx.x;
    const int lane = tid & 31;
    const int wid  = tid >> 5;
    const int b    = blockIdx.y;
    const int vb0  = blockIdx.x * 128;
    const float* __restrict__ xb = x + (size_t)b * NV * FIN;

    // ---- Stage fragment-ordered weights (2048 uint4, coalesced) -----------
    {
        const uint4* src = (const uint4*)g_wfrag;
        uint4*       dst = (uint4*)sW;
        #pragma unroll
        for (int i = 0; i < 8; ++i)
            dst[tid + i * 256] = src[tid + i * 256];
    }

    // ---- Stage 2048 neighbor ids (512 int4, coalesced, bound-guarded) -----
    {
        const int4* nsrc = (const int4*)neighbor;
        int4*       nd   = (int4*)sNid;
        #pragma unroll
        for (int i = 0; i < 2; ++i) {
            int li = tid + i * 256;                 // 0..511
            int gi = vb0 * (KNB / 4) + li;          // global int4 index
            int4 v = make_int4(0, 0, 0, 0);
            if (gi < NV * KNB / 4) v = __ldg(&nsrc[gi]);
            nd[li] = v;
        }
    }
    __syncthreads();

    // ---- Gather phase: warp = 16 verts, 2 at a time (32 LDG.64 in flight) -
    {
        const float s = 1.0f / (float)KNB;
        #pragma unroll
        for (int p = 0; p < 8; ++p) {
            const int vA = wid * 16 + 2 * p;
            const int vB = vA + 1;
            const int* la = &sNid[vA * KNB];
            const int* lb = &sNid[vB * KNB];
            float2 aA = make_float2(0.f, 0.f);
            float2 aB = make_float2(0.f, 0.f);
            #pragma unroll
            for (int k = 0; k < KNB; ++k) {
                const int ra = la[k];               // LDS broadcast, warp-uniform
                const int rb = lb[k];
                if (ra > 0) {                       // 0 = zero-pad row
                    float2 tv = *(const float2*)(xb + (size_t)(ra - 1) * FIN + lane * 2);
                    aA.x += tv.x; aA.y += tv.y;
                }
                if (rb > 0) {
                    float2 tv = *(const float2*)(xb + (size_t)(rb - 1) * FIN + lane * 2);
                    aB.x += tv.x; aB.y += tv.y;
                }
            }
            *(float2*)&sNbm[vA * NBM_STRIDE + lane * 2] = make_float2(aA.x * s, aA.y * s);
            *(float2*)&sNbm[vB * NBM_STRIDE + lane * 2] = make_float2(aB.x * s, aB.y * s);
        }
    }

    // ---- x A-fragments from global (issue before sync to overlap) ---------
    const int g  = lane >> 2;
    const int t  = lane & 3;
    const int r0 = vb0 + wid * 16 + g;
    const int r1 = r0 + 8;
    float f0[16], f1[16];
    #pragma unroll
    for (int j = 0; j < 16; ++j) {
        int c = t + 4 * j;
        f0[j] = (r0 < NV) ? __ldg(&xb[(size_t)r0 * FIN + c]) : 0.f;
        f1[j] = (r1 < NV) ? __ldg(&xb[(size_t)r1 * FIN + c]) : 0.f;
    }
    __syncthreads();

    // ---- Convert A-fragments to tf32 ---------------------------------------
    uint32_t ar0[16], ar1[16];
    #pragma unroll
    for (int j = 0; j < 16; ++j) {
        asm("cvt.rna.tf32.f32 %0, %1;" : "=r"(ar0[j]) : "f"(f0[j]));
        asm("cvt.rna.tf32.f32 %0, %1;" : "=r"(ar1[j]) : "f"(f1[j]));
    }
    // nbm A-fragments from smem (pad 68 -> conflict-free LDS.32)
    const int r0l = wid * 16 + g;
    const int r1l = r0l + 8;
    uint32_t nr0[16], nr1[16];
    #pragma unroll
    for (int j = 0; j < 16; ++j) {
        int c = t + 4 * j;
        float v0 = sNbm[r0l * NBM_STRIDE + c];
        float v1 = sNbm[r1l * NBM_STRIDE + c];
        asm("cvt.rna.tf32.f32 %0, %1;" : "=r"(nr0[j]) : "f"(v0));
        asm("cvt.rna.tf32.f32 %0, %1;" : "=r"(nr1[j]) : "f"(v1));
    }

    // ---- Mainloop + epilogue, split into two nt-halves (register cap) ------
    float* __restrict__ outb = out + (size_t)b * NV * COUT;
    #pragma unroll
    for (int h = 0; h < 2; ++h) {
        float accX[4][4] = {{0.f}};
        float accN[4][4] = {{0.f}};

        #pragma unroll
        for (int ks = 0; ks < 8; ++ks) {
            const uint32_t a0 = ar0[2 * ks], a1 = ar1[2 * ks];
            const uint32_t a2 = ar0[2 * ks + 1], a3 = ar1[2 * ks + 1];
            const uint32_t n0 = nr0[2 * ks], n1 = nr1[2 * ks];
            const uint32_t n2 = nr0[2 * ks + 1], n3 = nr1[2 * ks + 1];

            #pragma unroll
            for (int q = 0; q < 4; ++q) {
                const int nt = h * 4 + q;
                const uint2 bx = *(const uint2*)&sW[((0 * 8 + ks) * 8 + nt) * 64 + lane * 2];
                const uint2 bn = *(const uint2*)&sW[((1 * 8 + ks) * 8 + nt) * 64 + lane * 2];

                asm volatile(
                    "mma.sync.aligned.m16n8k8.row.col.f32.tf32.tf32.f32 "
                    "{%0,%1,%2,%3}, {%4,%5,%6,%7}, {%8,%9}, {%0,%1,%2,%3};"
                    : "+f"(accX[q][0]), "+f"(accX[q][1]),
                      "+f"(accX[q][2]), "+f"(accX[q][3])
                    : "r"(a0), "r"(a1), "r"(a2), "r"(a3),
                      "r"(bx.x), "r"(bx.y));
                asm volatile(
                    "mma.sync.aligned.m16n8k8.row.col.f32.tf32.tf32.f32 "
                    "{%0,%1,%2,%3}, {%4,%5,%6,%7}, {%8,%9}, {%0,%1,%2,%3};"
                    : "+f"(accN[q][0]), "+f"(accN[q][1]),
                      "+f"(accN[q][2]), "+f"(accN[q][3])
                    : "r"(n0), "r"(n1), "r"(n2), "r"(n3),
                      "r"(bn.x), "r"(bn.y));
            }
        }

        #pragma unroll
        for (int q = 0; q < 4; ++q) {
            const int nt = h * 4 + q;
            const int c  = nt * 8 + 2 * t;
            const float2 bv = *(const float2*)&bias[c];
            if (r0 < NV)
                *(float2*)&outb[(size_t)r0 * COUT + c] =
                    make_float2(accX[q][0] + accN[q][0] + bv.x,
                                accX[q][1] + accN[q][1] + bv.y);
            if (r1 < NV)
                *(float2*)&outb[(size_t)r1 * COUT + c] =
                    make_float2(accX[q][2] + accN[q][2] + bv.x,
                                accX[q][3] + accN[q][3] + bv.y);
        }
    }
}

extern "C" void kernel_launch(void* const* d_in, const int* in_sizes, int n_in,
                              void* d_out, int out_size)
{
    // metadata order: x, Wx, Wn, b, neighbor
    const float* x        = (const float*)d_in[0];
    const float* Wx       = (const float*)d_in[1];
    const float* Wn       = (const float*)d_in[2];
    const float* bias     = (const float*)d_in[3];
    const int*   neighbor = (const int*)d_in[4];
    float*       out      = (float*)d_out;

    cudaFuncSetAttribute(convnet_fused_tc,
                         cudaFuncAttributeMaxDynamicSharedMemorySize, SMEM_TOTAL);

    wfrag_build_kernel<<<64, 256>>>(Wx, Wn);

    dim3 grid((NV + 127) / 128, BATCH);         // 157 x 16
    convnet_fused_tc<<<grid, 256, SMEM_TOTAL>>>(x, bias, neighbor, out);
}

// round 10
// speedup vs baseline: 1.1795x; 1.1795x over previous
#include <cuda_runtime.h>
#include <cstdint>

#define BATCH 16
#define NV    20000
#define FIN   64
#define COUT  64
#define KNB   16

// Scratch: y = x @ Wn with a zero pad row at index 0.  [B][V+1][COUT]
__device__ float g_y[(size_t)BATCH * (NV + 1) * COUT];
// Weights in mma-fragment order: [mat(2)][ks(8)][nt(8)][lane(32)][2] tf32 bits
__device__ uint32_t g_wfrag[2 * 8 * 8 * 32 * 2];

// ---------------------------------------------------------------------------
// Pre-kernel: swizzle Wx/Wn into m16n8k8 B-fragment order (tf32),
// and zero the pad rows of g_y (row 0 of each batch).
// ---------------------------------------------------------------------------
__global__ void wfrag_build_kernel(const float* __restrict__ Wx,
                                   const float* __restrict__ Wn)
{
    int i = blockIdx.x * 256 + threadIdx.x;        // 0..16383
    int j    =  i        & 1;
    int lane = (i >> 1)  & 31;
    int nt   = (i >> 6)  & 7;
    int ks   = (i >> 9)  & 7;
    int mat  =  i >> 12;
    int k = (lane & 3) + 4 * j + 8 * ks;
    int n = (lane >> 2) + 8 * nt;
    const float* W = mat ? Wn : Wx;
    float v = W[k * COUT + n];
    uint32_t tv;
    asm("cvt.rna.tf32.f32 %0, %1;" : "=r"(tv) : "f"(v));
    g_wfrag[i] = tv;

    // Zero pad rows: 16 batches * 64 channels = 1024 floats
    if (i < BATCH * COUT) {
        int b = i >> 6;
        int c = i & 63;
        g_y[(size_t)b * (NV + 1) * COUT + c] = 0.f;
    }
}

// ---------------------------------------------------------------------------
// Kernel A: tensor-core dual GEMM. out = x@Wx + b (d_out), y = x@Wn (scratch)
// CTA = 128 verts x 64 cols, 8 warps; warp = 16 verts x 64 cols, K=64.
// ---------------------------------------------------------------------------
__global__ __launch_bounds__(256)
void gemm_tc_kernel(const float* __restrict__ x,
                    const float* __restrict__ bias,
                    float*       __restrict__ out)
{
    __shared__ uint32_t sW[2 * 8 * 8 * 32 * 2];    // 32 KB

    const int tid = threadIdx.x;

    // Stage fragment-ordered weights: 2048 uint4, 8 per thread, coalesced.
    {
        const uint4* src = (const uint4*)g_wfrag;
        uint4*       dst = (uint4*)sW;
        #pragma unroll
        for (int i = 0; i < 8; ++i)
            dst[tid + i * 256] = src[tid + i * 256];
    }
    __syncthreads();

    const int lane = tid & 31;
    const int wid  = tid >> 5;
    const int g    = lane >> 2;      // group id (row within m-tile)
    const int t    = lane & 3;       // thread-in-group (col phase)
    const int b    = blockIdx.y;
    const int vb   = blockIdx.x * 128 + wid * 16;
    const int r0   = vb + g;
    const int r1   = r0 + 8;

    const float* __restrict__ xb = x + (size_t)b * NV * FIN;

    // ---- Prefetch A: 2 rows x 16 cols (cols == t mod 4). 32 indep LDG.32 --
    float f0[16], f1[16];
    #pragma unroll
    for (int j = 0; j < 16; ++j) {
        int c = t + 4 * j;
        f0[j] = (r0 < NV) ? __ldg(&xb[(size_t)r0 * FIN + c]) : 0.f;
        f1[j] = (r1 < NV) ? __ldg(&xb[(size_t)r1 * FIN + c]) : 0.f;
    }
    uint32_t ar0[16], ar1[16];
    #pragma unroll
    for (int j = 0; j < 16; ++j) {
        asm("cvt.rna.tf32.f32 %0, %1;" : "=r"(ar0[j]) : "f"(f0[j]));
        asm("cvt.rna.tf32.f32 %0, %1;" : "=r"(ar1[j]) : "f"(f1[j]));
    }

    // ---- Mainloop: 8 k-steps x 8 n-tiles x 2 matrices ----------------------
    float accX[8][4] = {{0.f}};
    float accN[8][4] = {{0.f}};

    #pragma unroll
    for (int ks = 0; ks < 8; ++ks) {
        const uint32_t a0 = ar0[2 * ks];
        const uint32_t a1 = ar1[2 * ks];
        const uint32_t a2 = ar0[2 * ks + 1];
        const uint32_t a3 = ar1[2 * ks + 1];

        #pragma unroll
        for (int nt = 0; nt < 8; ++nt) {
            const uint2 bx = *(const uint2*)&sW[((0 * 8 + ks) * 8 + nt) * 64 + lane * 2];
            const uint2 bn = *(const uint2*)&sW[((1 * 8 + ks) * 8 + nt) * 64 + lane * 2];

            asm volatile(
                "mma.sync.aligned.m16n8k8.row.col.f32.tf32.tf32.f32 "
                "{%0,%1,%2,%3}, {%4,%5,%6,%7}, {%8,%9}, {%0,%1,%2,%3};"
                : "+f"(accX[nt][0]), "+f"(accX[nt][1]),
                  "+f"(accX[nt][2]), "+f"(accX[nt][3])
                : "r"(a0), "r"(a1), "r"(a2), "r"(a3),
                  "r"(bx.x), "r"(bx.y));
            asm volatile(
                "mma.sync.aligned.m16n8k8.row.col.f32.tf32.tf32.f32 "
                "{%0,%1,%2,%3}, {%4,%5,%6,%7}, {%8,%9}, {%0,%1,%2,%3};"
                : "+f"(accN[nt][0]), "+f"(accN[nt][1]),
                  "+f"(accN[nt][2]), "+f"(accN[nt][3])
                : "r"(a0), "r"(a1), "r"(a2), "r"(a3),
                  "r"(bn.x), "r"(bn.y));
        }
    }

    // ---- Epilogue: out rows; y rows shifted +1 (row 0 = zero pad) ---------
    float* __restrict__ outb = out + (size_t)b * NV * COUT;
    float* __restrict__ yb   = g_y + (size_t)b * (NV + 1) * COUT;
    #pragma unroll
    for (int nt = 0; nt < 8; ++nt) {
        const int c = nt * 8 + 2 * t;
        const float2 bv = *(const float2*)&bias[c];
        if (r0 < NV) {
            *(float2*)&outb[(size_t)r0 * COUT + c] =
                make_float2(accX[nt][0] + bv.x, accX[nt][1] + bv.y);
            *(float2*)&yb[(size_t)(r0 + 1) * COUT + c] =
                make_float2(accN[nt][0], accN[nt][1]);
        }
        if (r1 < NV) {
            *(float2*)&outb[(size_t)r1 * COUT + c] =
                make_float2(accX[nt][2] + bv.x, accX[nt][3] + bv.y);
            *(float2*)&yb[(size_t)(r1 + 1) * COUT + c] =
                make_float2(accN[nt][2], accN[nt][3]);
        }
    }
}

// ---------------------------------------------------------------------------
// Kernel B: out[b,v,:] += (1/K) * mean of y rows neighbor[v][k] (0 = pad row).
// Warp = 4 vertices. Per k-pair one LDG.128 covers 2 neighbor rows
// (lanes 0-15 -> even k, lanes 16-31 -> odd k). No guards, no branches.
// ---------------------------------------------------------------------------
__global__ __launch_bounds__(256)
void gather_add_kernel(const int* __restrict__ neighbor,
                       float*     __restrict__ out)
{
    __shared__ int sN[512];   // 32 verts * 16 ids

    const int tid  = threadIdx.x;
    const int warp = tid >> 5;
    const int lane = tid & 31;
    const int half = lane >> 4;          // 0 = even-k rows, 1 = odd-k rows
    const int l16  = lane & 15;
    const int vblk = blockIdx.x * 32;    // 625 * 32 = 20000 exactly
    const int v0   = vblk + warp * 4;
    const int b    = blockIdx.y;

    // Stage this CTA's 512 neighbor ids (one coalesced 2KB read).
    ((int2*)sN)[tid] = __ldg((const int2*)&neighbor[vblk * KNB] + tid);
    __syncthreads();

    const float* __restrict__ yb = g_y + (size_t)b * (NV + 1) * COUT;

    float4 acc0 = make_float4(0.f, 0.f, 0.f, 0.f);
    float4 acc1 = acc0, acc2 = acc0, acc3 = acc0;

    const int2* ids = (const int2*)&sN[warp * 4 * KNB];

    #pragma unroll
    for (int p = 0; p < 8; ++p) {
        // Vertex 0..3; ids[vv*8+p] = neighbors (2p, 2p+1) of vertex vv.
        const int2 i0 = ids[0 * 8 + p];          // uniform LDS.64 -> broadcast
        const int2 i1 = ids[1 * 8 + p];
        const int2 i2 = ids[2 * 8 + p];
        const int2 i3 = ids[3 * 8 + p];
        const int r0 = half ? i0.y : i0.x;       // id; 0 = zero pad row
        const int r1 = half ? i1.y : i1.x;
        const int r2 = half ? i2.y : i2.x;
        const int r3 = half ? i3.y : i3.x;

        const float4 t0 = *(const float4*)(yb + (size_t)r0 * COUT + l16 * 4);
        const float4 t1 = *(const float4*)(yb + (size_t)r1 * COUT + l16 * 4);
        const float4 t2 = *(const float4*)(yb + (size_t)r2 * COUT + l16 * 4);
        const float4 t3 = *(const float4*)(yb + (size_t)r3 * COUT + l16 * 4);

        acc0.x += t0.x; acc0.y += t0.y; acc0.z += t0.z; acc0.w += t0.w;
        acc1.x += t1.x; acc1.y += t1.y; acc1.z += t1.z; acc1.w += t1.w;
        acc2.x += t2.x; acc2.y += t2.y; acc2.z += t2.z; acc2.w += t2.w;
        acc3.x += t3.x; acc3.y += t3.y; acc3.z += t3.z; acc3.w += t3.w;
    }

    // Combine even/odd halves: butterfly across lane 16.
    #pragma unroll
    for (int c = 0; c < 4; ++c) {
        ((float*)&acc0)[c] += __shfl_xor_sync(0xffffffffu, ((float*)&acc0)[c], 16);
        ((float*)&acc1)[c] += __shfl_xor_sync(0xffffffffu, ((float*)&acc1)[c], 16);
        ((float*)&acc2)[c] += __shfl_xor_sync(0xffffffffu, ((float*)&acc2)[c], 16);
        ((float*)&acc3)[c] += __shfl_xor_sync(0xffffffffu, ((float*)&acc3)[c], 16);
    }

    // Pairwise RMW: low half -> vertex v0+0 / v0+2, high half -> v0+1 / v0+3.
    const float s = 1.0f / (float)KNB;
    const float4 sAB = half ? acc1 : acc0;
    const float4 sCD = half ? acc3 : acc2;

    float* opAB = out + ((size_t)b * NV + v0 + half)     * COUT + l16 * 4;
    float* opCD = out + ((size_t)b * NV + v0 + 2 + half) * COUT + l16 * 4;

    float4 oAB = *(const float4*)opAB;
    float4 oCD = *(const float4*)opCD;
    oAB.x += sAB.x * s; oAB.y += sAB.y * s; oAB.z += sAB.z * s; oAB.w += sAB.w * s;
    oCD.x += sCD.x * s; oCD.y += sCD.y * s; oCD.z += sCD.z * s; oCD.w += sCD.w * s;
    *(float4*)opAB = oAB;
    *(float4*)opCD = oCD;
}

extern "C" void kernel_launch(void* const* d_in, const int* in_sizes, int n_in,
                              void* d_out, int out_size)
{
    // metadata order: x, Wx, Wn, b, neighbor
    const float* x        = (const float*)d_in[0];
    const float* Wx       = (const float*)d_in[1];
    const float* Wn       = (const float*)d_in[2];
    const float* bias     = (const float*)d_in[3];
    const int*   neighbor = (const int*)d_in[4];
    float*       out      = (float*)d_out;

    wfrag_build_kernel<<<64, 256>>>(Wx, Wn);

    dim3 gridA((NV + 127) / 128, BATCH);        // 157 x 16
    gemm_tc_kernel<<<gridA, 256>>>(x, bias, out);

    dim3 gridB(NV / 32, BATCH);                 // 625 x 16
    gather_add_kernel<<<gridB, 256>>>(neighbor, out);
}